// round 2
// baseline (speedup 1.0000x reference)
#include <cuda_runtime.h>

// Problem: out[n,o,h,w] = relu( sum_c fea[n,c,h,w] * W[o,c,0,4] + b[o] )
// Shapes: fea (8, 2048, 64, 64) f32, W (512, 2048, 1, 9) f32, b (512) f32
// => per-batch GEMM: Out[512,4096] = Wc[512,2048] @ Fea_n[2048,4096], bias+relu

#define GM 512      // out channels (M)
#define GN 4096     // pixels per image (N = 64*64)
#define GK 2048     // in channels (K)
#define NBATCH 8

#define BM 128
#define BN 128
#define BK 16
#define TM 8
#define TN 8
#define NTHREADS 256

// Compact Wc = W[:, :, 0, 4] (stride-9 gather) into a dense [512,2048] buffer.
__device__ float g_Wc[GM * GK];

__global__ void pack_wc_kernel(const float* __restrict__ W) {
    int i = blockIdx.x * blockDim.x + threadIdx.x;
    if (i < GM * GK) {
        g_Wc[i] = W[(size_t)i * 9 + 4];
    }
}

__global__ __launch_bounds__(NTHREADS, 2)
void sgemm_bias_relu_kernel(const float* __restrict__ fea,
                            const float* __restrict__ bias,
                            float* __restrict__ out) {
    const int n = blockIdx.z;
    const float* __restrict__ B = fea + (size_t)n * GK * GN;   // [K, N], N contiguous
    float* __restrict__ C = out + (size_t)n * GM * GN;         // [M, N]

    const int rowBlk = blockIdx.y * BM;   // M offset
    const int colBlk = blockIdx.x * BN;   // N offset

    __shared__ float As[BK][BM];   // A tile, transposed: [k][m]
    __shared__ float Bs[BK][BN];   // B tile: [k][n]

    const int tid = threadIdx.x;

    // ---- global-load index mapping ----
    // A tile (BM x BK = 128 x 16): each thread loads 8 contiguous floats of one row.
    const int aRow  = tid & 127;            // 0..127 (M within tile)
    const int aCol0 = (tid >> 7) * 8;       // 0 or 8 (K within tile)
    const float* Aptr = g_Wc + (size_t)(rowBlk + aRow) * GK + aCol0;

    // B tile (BK x BN = 16 x 128): 512 float4s, 2 per thread.
    const int bRow0 = tid >> 5;             // 0..7, second load adds +8
    const int bCol  = (tid & 31) * 4;       // 0..124
    const float* Bptr = B + (size_t)bRow0 * GN + colBlk + bCol;

    // ---- compute thread mapping (16 x 16 threads, 8x8 micro-tile each) ----
    const int tx = tid & 15;                // N direction
    const int ty = tid >> 4;                // M direction
    const int mBase = ty * TM;
    const int nBase = tx * TN;

    float acc[TM][TN];
    #pragma unroll
    for (int i = 0; i < TM; ++i)
        #pragma unroll
        for (int j = 0; j < TN; ++j)
            acc[i][j] = 0.0f;

    for (int kt = 0; kt < GK; kt += BK) {
        // global loads for this tile
        float4 a0 = *(const float4*)(Aptr + kt);
        float4 a1 = *(const float4*)(Aptr + kt + 4);
        float4 b0 = *(const float4*)(Bptr + (size_t)kt * GN);
        float4 b1 = *(const float4*)(Bptr + (size_t)(kt + 8) * GN);

        __syncthreads();   // previous iteration's compute done before overwrite

        // store A transposed: As[k][m]; warp writes consecutive m -> conflict-free
        As[aCol0 + 0][aRow] = a0.x;
        As[aCol0 + 1][aRow] = a0.y;
        As[aCol0 + 2][aRow] = a0.z;
        As[aCol0 + 3][aRow] = a0.w;
        As[aCol0 + 4][aRow] = a1.x;
        As[aCol0 + 5][aRow] = a1.y;
        As[aCol0 + 6][aRow] = a1.z;
        As[aCol0 + 7][aRow] = a1.w;

        *(float4*)&Bs[bRow0][bCol]     = b0;
        *(float4*)&Bs[bRow0 + 8][bCol] = b1;

        __syncthreads();

        #pragma unroll
        for (int kk = 0; kk < BK; ++kk) {
            float a_frag[TM], b_frag[TN];
            *(float4*)&a_frag[0] = *(const float4*)&As[kk][mBase];
            *(float4*)&a_frag[4] = *(const float4*)&As[kk][mBase + 4];
            *(float4*)&b_frag[0] = *(const float4*)&Bs[kk][nBase];
            *(float4*)&b_frag[4] = *(const float4*)&Bs[kk][nBase + 4];
            #pragma unroll
            for (int i = 0; i < TM; ++i)
                #pragma unroll
                for (int j = 0; j < TN; ++j)
                    acc[i][j] = fmaf(a_frag[i], b_frag[j], acc[i][j]);
        }
    }

    // ---- epilogue: bias + relu, vectorized stores ----
    #pragma unroll
    for (int i = 0; i < TM; ++i) {
        const int row = rowBlk + mBase + i;
        const float bv = bias[row];
        float* crow = C + (size_t)row * GN + colBlk + nBase;
        #pragma unroll
        for (int j4 = 0; j4 < TN; j4 += 4) {
            float4 v;
            v.x = fmaxf(acc[i][j4 + 0] + bv, 0.0f);
            v.y = fmaxf(acc[i][j4 + 1] + bv, 0.0f);
            v.z = fmaxf(acc[i][j4 + 2] + bv, 0.0f);
            v.w = fmaxf(acc[i][j4 + 3] + bv, 0.0f);
            *(float4*)(crow + j4) = v;
        }
    }
}

extern "C" void kernel_launch(void* const* d_in, const int* in_sizes, int n_in,
                              void* d_out, int out_size) {
    const float* fea  = (const float*)d_in[0];   // (8, 2048, 64, 64)
    const float* W    = (const float*)d_in[1];   // (512, 2048, 1, 9)
    const float* bias = (const float*)d_in[2];   // (512,)
    float* out = (float*)d_out;                  // (8, 512, 64, 64)

    pack_wc_kernel<<<(GM * GK + 255) / 256, 256>>>(W);

    dim3 grid(GN / BN, GM / BM, NBATCH);   // (32, 4, 8)
    sgemm_bias_relu_kernel<<<grid, NTHREADS>>>(fea, bias, out);
}

// round 6
// speedup vs baseline: 5.6472x; 5.6472x over previous
#include <cuda_runtime.h>
#include <cuda_fp16.h>
#include <cstdint>
#include <cstring>

// out[n,o,p] = relu( sum_c fea[n,c,p] * W[o,c,0,4] + b[o] )
// GEMM per batch: D[512,4096] = Wc[512,2048] @ fea_n[2048,4096]
// fp16 mma.sync.m16n8k16, fp32 accumulate. No sm_103a-only (tcgen05) features.

#define GM 512
#define GN 4096
#define GK 2048
#define NB 8

#define BM 128
#define BN 128
#define BK 32
#define STAGES 3
#define NITER (GK / BK)   // 64
#define NMB (GM / BM)     // 4
#define NPB (GN / BN)     // 32

// smem layout (bytes): padded rows for conflict-free ldmatrix
#define A_ROW_B 80                      // 32 halves (64B) + 16B pad
#define A_TILE_B (BM * A_ROW_B)         // 10240
#define B_ROW_B 272                     // 128 halves (256B) + 16B pad
#define B_TILE_B (BK * B_ROW_B)         // 8704
#define STAGE_B (A_TILE_B + B_TILE_B)   // 18944
#define SMEM_B (STAGES * STAGE_B)       // 56832

__device__ __align__(16) __half g_Wh[GM * GK];                 // 2 MB
__device__ __align__(16) __half g_feaH[(size_t)NB * GK * GN];  // 134 MB

// ---------------------------------------------------------------------------
__device__ __forceinline__ uint32_t smem_u32(const void* p) {
    uint32_t a;
    asm("{ .reg .u64 t; cvta.to.shared.u64 t, %1; cvt.u32.u64 %0, t; }" : "=r"(a) : "l"(p));
    return a;
}
__device__ __forceinline__ void cp16(uint32_t dst, const void* src) {
    asm volatile("cp.async.cg.shared.global [%0], [%1], 16;" :: "r"(dst), "l"(src));
}
#define CP_COMMIT() asm volatile("cp.async.commit_group;" ::: "memory")
template <int N>
__device__ __forceinline__ void cp_wait() {
    asm volatile("cp.async.wait_group %0;" :: "n"(N) : "memory");
}

__device__ __forceinline__ void ldmA(uint32_t* r, uint32_t addr) {
    asm volatile("ldmatrix.sync.aligned.m8n8.x4.shared.b16 {%0,%1,%2,%3}, [%4];"
        : "=r"(r[0]), "=r"(r[1]), "=r"(r[2]), "=r"(r[3]) : "r"(addr));
}
__device__ __forceinline__ void ldmBT(uint32_t* r, uint32_t addr) {
    asm volatile("ldmatrix.sync.aligned.m8n8.x4.trans.shared.b16 {%0,%1,%2,%3}, [%4];"
        : "=r"(r[0]), "=r"(r[1]), "=r"(r[2]), "=r"(r[3]) : "r"(addr));
}
__device__ __forceinline__ void mma16816(float* c, const uint32_t* a, uint32_t b0, uint32_t b1) {
    asm volatile("mma.sync.aligned.m16n8k16.row.col.f32.f16.f16.f32 "
        "{%0,%1,%2,%3}, {%4,%5,%6,%7}, {%8,%9}, {%0,%1,%2,%3};"
        : "+f"(c[0]), "+f"(c[1]), "+f"(c[2]), "+f"(c[3])
        : "r"(a[0]), "r"(a[1]), "r"(a[2]), "r"(a[3]), "r"(b0), "r"(b1));
}

// ---------------------------------------------------------------------------
// Pack Wc = W[:,:,0,4] -> fp16 row-major [M][K]
__global__ void pack_w_kernel(const float* __restrict__ W) {
    int i = blockIdx.x * blockDim.x + threadIdx.x;
    if (i < GM * GK) g_Wh[i] = __float2half_rn(W[(size_t)i * 9 + 4]);
}

// Convert fea fp32 -> fp16 (pure streaming)
__global__ __launch_bounds__(256)
void convert_fea_kernel(const float* __restrict__ fea) {
    size_t i = ((size_t)blockIdx.x * 256 + threadIdx.x) * 8;
    float4 f0 = *(const float4*)(fea + i);
    float4 f1 = *(const float4*)(fea + i + 4);
    __half2 h[4];
    h[0] = __floats2half2_rn(f0.x, f0.y);
    h[1] = __floats2half2_rn(f0.z, f0.w);
    h[2] = __floats2half2_rn(f1.x, f1.y);
    h[3] = __floats2half2_rn(f1.z, f1.w);
    uint4 v;
    memcpy(&v, h, 16);
    *(uint4*)(g_feaH + i) = v;
}

// ---------------------------------------------------------------------------
__global__ __launch_bounds__(256, 2)
void gemm_kernel(const float* __restrict__ bias, float* __restrict__ out) {
    extern __shared__ char smem[];
    const uint32_t sb = smem_u32(smem);

    const int tid  = threadIdx.x;
    const int wid  = tid >> 5;
    const int lane = tid & 31;
    const int mblk = blockIdx.x, pblk = blockIdx.y, nb = blockIdx.z;
    const int wm = wid & 1;        // 2 warps in M (64 rows each)
    const int wn = wid >> 1;       // 4 warps in N (32 cols each)

    const __half* Asrc = g_Wh + (size_t)mblk * BM * GK;                 // [m][k]
    const __half* Bsrc = g_feaH + (size_t)nb * GK * GN + pblk * BN;     // [k][n]

    // cp.async chunk mapping (each thread: 2 A-chunks + 2 B-chunks per stage)
    const int aM  = wid * 8 + (lane & 7);      // A row (first of pair), +64 for second
    const int aKc = (lane >> 3) & 3;           // A 16B-chunk within row
    const int bK  = tid >> 4;                  // B row (first), +16 for second
    const int bNc = tid & 15;                  // B 16B-chunk within row

    auto issue_stage = [&](int s, int kchunk) {
        const int k0 = kchunk * BK;
        uint32_t aBase = sb + s * STAGE_B;
        uint32_t bBase = aBase + A_TILE_B;
        cp16(aBase + aM * A_ROW_B + aKc * 16,
             Asrc + (size_t)aM * GK + k0 + aKc * 8);
        cp16(aBase + (aM + 64) * A_ROW_B + aKc * 16,
             Asrc + (size_t)(aM + 64) * GK + k0 + aKc * 8);
        cp16(bBase + bK * B_ROW_B + bNc * 16,
             Bsrc + (size_t)(k0 + bK) * GN + bNc * 8);
        cp16(bBase + (bK + 16) * B_ROW_B + bNc * 16,
             Bsrc + (size_t)(k0 + bK + 16) * GN + bNc * 8);
        CP_COMMIT();
    };

    float acc[4][4][4];
    #pragma unroll
    for (int mt = 0; mt < 4; ++mt)
        #pragma unroll
        for (int nt = 0; nt < 4; ++nt)
            #pragma unroll
            for (int j = 0; j < 4; ++j) acc[mt][nt][j] = 0.0f;

    issue_stage(0, 0);
    issue_stage(1, 1);

    const uint32_t aLdOff = (uint32_t)(wm * 64 + (lane & 15)) * A_ROW_B + ((lane >> 4) * 8) * 2;
    const uint32_t bLdOff = (uint32_t)(lane & 15) * B_ROW_B + (wn * 32 + (lane >> 4) * 8) * 2;

    for (int i = 0; i < NITER; ++i) {
        const int s = i % STAGES;
        if (i < NITER - 1) cp_wait<1>(); else cp_wait<0>();
        __syncthreads();

        if (i + 2 < NITER) issue_stage((i + 2) % STAGES, i + 2);

        const uint32_t aBase = sb + s * STAGE_B;
        const uint32_t bBase = aBase + A_TILE_B;

        #pragma unroll
        for (int ks = 0; ks < 2; ++ks) {
            const int k0 = ks * 16;
            uint32_t afr[4][4];
            #pragma unroll
            for (int mt = 0; mt < 4; ++mt)
                ldmA(afr[mt], aBase + aLdOff + (uint32_t)mt * 16 * A_ROW_B + k0 * 2);
            uint32_t bfr[2][4];
            uint32_t bAddr = bBase + bLdOff + (uint32_t)k0 * B_ROW_B;
            ldmBT(bfr[0], bAddr);        // n-tiles 0,1
            ldmBT(bfr[1], bAddr + 32);   // n-tiles 2,3
            #pragma unroll
            for (int mt = 0; mt < 4; ++mt)
                #pragma unroll
                for (int nt = 0; nt < 4; ++nt)
                    mma16816(acc[mt][nt], afr[mt],
                             bfr[nt >> 1][(nt & 1) * 2], bfr[nt >> 1][(nt & 1) * 2 + 1]);
        }
    }

    // ---- epilogue: bias + relu ----
    const int row0 = mblk * BM + wm * 64 + (lane >> 2);
    const int col0 = pblk * BN + wn * 32 + (lane & 3) * 2;
    #pragma unroll
    for (int mt = 0; mt < 4; ++mt) {
        const int r = row0 + mt * 16;
        const float bv0 = bias[r];
        const float bv1 = bias[r + 8];
        float* p0 = out + ((size_t)nb * GM + r) * GN + col0;
        float* p1 = p0 + (size_t)8 * GN;
        #pragma unroll
        for (int nt = 0; nt < 4; ++nt) {
            float2 v0, v1;
            v0.x = fmaxf(acc[mt][nt][0] + bv0, 0.0f);
            v0.y = fmaxf(acc[mt][nt][1] + bv0, 0.0f);
            v1.x = fmaxf(acc[mt][nt][2] + bv1, 0.0f);
            v1.y = fmaxf(acc[mt][nt][3] + bv1, 0.0f);
            *(float2*)(p0 + nt * 8) = v0;
            *(float2*)(p1 + nt * 8) = v1;
        }
    }
}

// ---------------------------------------------------------------------------
extern "C" void kernel_launch(void* const* d_in, const int* in_sizes, int n_in,
                              void* d_out, int out_size) {
    const float* fea  = (const float*)d_in[0];
    const float* W    = (const float*)d_in[1];
    const float* bias = (const float*)d_in[2];
    float* out = (float*)d_out;

    static bool attr_set = false;
    if (!attr_set) {
        cudaFuncSetAttribute(gemm_kernel, cudaFuncAttributeMaxDynamicSharedMemorySize, SMEM_B);
        attr_set = true;
    }

    pack_w_kernel<<<(GM * GK + 255) / 256, 256>>>(W);
    {
        size_t total = (size_t)NB * GK * GN;            // 67108864
        int blocks = (int)(total / (256 * 8));          // 32768
        convert_fea_kernel<<<blocks, 256>>>(fea);
    }
    gemm_kernel<<<dim3(NMB, NPB, NB), 256, SMEM_B>>>(bias, out);
}